// round 6
// baseline (speedup 1.0000x reference)
#include <cuda_runtime.h>

// DyDepthwiseConvAtten: B=1024, N=100, C=256, K=3
//   K1 (wcalc): half-warp per row, grouped butterfly (R5 version, 33us).
//   K2 (conv+LN): NEW half-warp per row, 16 ch/lane, in-place conv,
//      grouped (sum,sq) reduce shared across the two rows -> 4.5 SHFL/row.

#define ROWS_TOTAL (1024 * 100)
#define CH 256
#define LN_EPS 1e-5f

// per-row conv taps (k0,k1,k2,pad) — 1.6 MB scratch, L2-resident
__device__ float4 g_w[ROWS_TOTAL];

// ---------------- kernel 1: dynamic taps, half-warp per row ----------------
__global__ __launch_bounds__(256)
void dydw_wcalc_kernel(const float* __restrict__ query,
                       const float* __restrict__ W_w,
                       const float* __restrict__ b_w)
{
    const int lane    = threadIdx.x & 31;
    const int hlane   = lane & 15;
    const int half    = lane >> 4;
    const int warp    = (blockIdx.x * blockDim.x + threadIdx.x) >> 5;
    const int nwarps  = (gridDim.x * blockDim.x) >> 5;   // 12800
    const int cbase4  = hlane * 4;

    float w0r[16], w1r[16], w2r[16];
    #pragma unroll
    for (int i = 0; i < 4; i++) {
        const float4 a = __ldg((const float4*)W_w + cbase4 + i);
        const float4 b = __ldg((const float4*)W_w + 64 + cbase4 + i);
        const float4 c = __ldg((const float4*)W_w + 128 + cbase4 + i);
        w0r[i*4+0]=a.x; w0r[i*4+1]=a.y; w0r[i*4+2]=a.z; w0r[i*4+3]=a.w;
        w1r[i*4+0]=b.x; w1r[i*4+1]=b.y; w1r[i*4+2]=b.z; w1r[i*4+3]=b.w;
        w2r[i*4+0]=c.x; w2r[i*4+1]=c.y; w2r[i*4+2]=c.z; w2r[i*4+3]=c.w;
    }
    const int grp = (lane >> 2) & 3;
    const float bias = (grp < 3) ? __ldg(&b_w[grp]) : 0.0f;

    for (int rp = warp * 2; rp < ROWS_TOTAL; rp += 2 * nwarps) {
        const int row = rp + half;
        const float4* qrow = (const float4*)(query + (size_t)row * CH);
        float4 q4[4];
        #pragma unroll
        for (int i = 0; i < 4; i++) q4[i] = qrow[cbase4 + i];

        float s0 = 0.f, s1 = 0.f, s2 = 0.f;
        #pragma unroll
        for (int i = 0; i < 4; i++) {
            const float q[4] = {q4[i].x, q4[i].y, q4[i].z, q4[i].w};
            #pragma unroll
            for (int u = 0; u < 4; u++) {
                s0 = fmaf(q[u], w0r[i*4+u], s0);
                s1 = fmaf(q[u], w1r[i*4+u], s1);
                s2 = fmaf(q[u], w2r[i*4+u], s2);
            }
        }
        #pragma unroll
        for (int off = 8; off >= 4; off >>= 1) {
            s0 += __shfl_xor_sync(0xffffffffu, s0, off);
            s1 += __shfl_xor_sync(0xffffffffu, s1, off);
            s2 += __shfl_xor_sync(0xffffffffu, s2, off);
        }
        float t = (grp == 0) ? s0 : (grp == 1) ? s1 : (grp == 2) ? s2 : s0;
        t += __shfl_xor_sync(0xffffffffu, t, 2);
        t += __shfl_xor_sync(0xffffffffu, t, 1);

        if ((lane & 3) == 0) {
            const float val = (grp < 3) ? (t + bias) : 0.0f;
            ((float*)&g_w[row])[grp] = val;
        }
    }
}

// ---------------- kernel 2: conv + LayerNorm, half-warp per row ----------------
__global__ __launch_bounds__(256)
void dydw_conv_ln_kernel(const float* __restrict__ value,
                         const float* __restrict__ gamma,
                         const float* __restrict__ beta,
                         float* __restrict__ out)
{
    const int lane   = threadIdx.x & 31;
    const int hlane  = lane & 15;
    const int half   = lane >> 4;
    const int warp   = (blockIdx.x * blockDim.x + threadIdx.x) >> 5;
    const int nwarps = (gridDim.x * blockDim.x) >> 5;   // 12800
    const int cbase4 = hlane * 4;                       // first float4 of 16 channels

    for (int rp = warp * 2; rp < ROWS_TOTAL; rp += 2 * nwarps) {   // 4 iters
        const int row = rp + half;
        const float4 w4 = __ldg(&g_w[row]);
        const float k0 = w4.x, k1 = w4.y, k2 = w4.z;

        const float4* vrow = (const float4*)(value + (size_t)row * CH);
        float v[16];
        #pragma unroll
        for (int i = 0; i < 4; i++) {
            const float4 x = vrow[cbase4 + i];
            v[i*4+0] = x.x; v[i*4+1] = x.y; v[i*4+2] = x.z; v[i*4+3] = x.w;
        }

        // halo (zero pad at row edges = half-warp edges)
        float left  = __shfl_up_sync(0xffffffffu, v[15], 1);
        float right = __shfl_down_sync(0xffffffffu, v[0], 1);
        if (hlane == 0)  left = 0.f;
        if (hlane == 15) right = 0.f;

        // in-place conv: v[i] <- k0*v[i-1] + k1*v[i] + k2*v[i+1]
        float sum = 0.f, sq = 0.f;
        float prev = left;
        #pragma unroll
        for (int i = 0; i < 16; i++) {
            const float cur = v[i];
            const float vp  = (i == 15) ? right : v[i + 1];
            const float o   = fmaf(k0, prev, fmaf(k1, cur, k2 * vp));
            v[i] = o;
            sum += o;
            sq = fmaf(o, o, sq);
            prev = cur;
        }

        // grouped reduce within each 16-lane half, both rows in lockstep:
        // {8} on sum,sq; then 8-lane groups (closed under {4,2,1}) finish
        // sum (lanes &8==0) and sq (lanes &8!=0).
        sum += __shfl_xor_sync(0xffffffffu, sum, 8);
        sq  += __shfl_xor_sync(0xffffffffu, sq,  8);
        float t = ((lane & 8) == 0) ? sum : sq;
        t += __shfl_xor_sync(0xffffffffu, t, 4);
        t += __shfl_xor_sync(0xffffffffu, t, 2);
        t += __shfl_xor_sync(0xffffffffu, t, 1);
        const int base = lane & 16;
        const float tot_sum = __shfl_sync(0xffffffffu, t, base);
        const float tot_sq  = __shfl_sync(0xffffffffu, t, base + 8);

        const float mean = tot_sum * (1.f / CH);
        const float var  = tot_sq * (1.f / CH) - mean * mean;
        const float rstd = rsqrtf(var + LN_EPS);

        // normalize + affine; gamma/beta stream from L1 (1KB resident)
        float4* orow = (float4*)(out + (size_t)row * CH);
        #pragma unroll
        for (int i = 0; i < 4; i++) {
            const float4 g = __ldg((const float4*)gamma + cbase4 + i);
            const float4 b = __ldg((const float4*)beta  + cbase4 + i);
            float4 y;
            y.x = fmaf((v[i*4+0] - mean) * rstd, g.x, b.x);
            y.y = fmaf((v[i*4+1] - mean) * rstd, g.y, b.y);
            y.z = fmaf((v[i*4+2] - mean) * rstd, g.z, b.z);
            y.w = fmaf((v[i*4+3] - mean) * rstd, g.w, b.w);
            orow[cbase4 + i] = y;
        }
    }
}

extern "C" void kernel_launch(void* const* d_in, const int* in_sizes, int n_in,
                              void* d_out, int out_size)
{
    const float* query = (const float*)d_in[0];
    const float* value = (const float*)d_in[1];
    const float* W_w   = (const float*)d_in[2];
    const float* b_w   = (const float*)d_in[3];
    const float* gamma = (const float*)d_in[4];
    const float* beta  = (const float*)d_in[5];
    float* out = (float*)d_out;

    dydw_wcalc_kernel<<<1600, 256>>>(query, W_w, b_w);            // 2 rows/warp/iter
    dydw_conv_ln_kernel<<<1600, 256>>>(value, gamma, beta, out);  // 2 rows/warp/iter
}

// round 8
// speedup vs baseline: 1.0363x; 1.0363x over previous
#include <cuda_runtime.h>

// DyDepthwiseConvAtten: B=1024, N=100, C=256, K=3
//   K1 (wcalc): half-warp per row; W streamed from L1 每-iter (no resident
//      W registers -> occupancy up). Grouped butterfly = 4 SHFL/row.
//   K2 (conv+LN): R2 version verbatim (measured 39.0us, 48 regs, occ 55%).

#define ROWS_TOTAL (1024 * 100)
#define CH 256
#define LN_EPS 1e-5f

// per-row conv taps (k0,k1,k2,pad) — 1.6 MB scratch, L2-resident
__device__ float4 g_w[ROWS_TOTAL];

// ---------------- kernel 1: dynamic taps, half-warp per row ----------------
__global__ __launch_bounds__(256)
void dydw_wcalc_kernel(const float* __restrict__ query,
                       const float* __restrict__ W_w,
                       const float* __restrict__ b_w)
{
    const int lane    = threadIdx.x & 31;
    const int hlane   = lane & 15;
    const int half    = lane >> 4;
    const int warp    = (blockIdx.x * blockDim.x + threadIdx.x) >> 5;
    const int nwarps  = (gridDim.x * blockDim.x) >> 5;   // 12800
    const int cbase4  = hlane * 4;

    const float4* W0 = (const float4*)W_w + cbase4;        // tap 0, this lane's 16 ch
    const float4* W1 = (const float4*)W_w + 64 + cbase4;   // tap 1
    const float4* W2 = (const float4*)W_w + 128 + cbase4;  // tap 2

    const int grp = (lane >> 2) & 3;
    const float bias = (grp < 3) ? __ldg(&b_w[grp]) : 0.0f;

    for (int rp = warp * 2; rp < ROWS_TOTAL; rp += 2 * nwarps) {   // 4 iters
        const int row = rp + half;
        const float4* qrow = (const float4*)(query + (size_t)row * CH);

        // issue all 4 q loads up front (MLP=4, DRAM stream)
        float4 q4[4];
        #pragma unroll
        for (int i = 0; i < 4; i++) q4[i] = qrow[cbase4 + i];

        float s0 = 0.f, s1 = 0.f, s2 = 0.f;
        #pragma unroll
        for (int i = 0; i < 4; i++) {
            const float4 a = __ldg(&W0[i]);    // L1-resident (3KB total)
            const float4 b = __ldg(&W1[i]);
            const float4 c = __ldg(&W2[i]);
            const float4 q = q4[i];
            s0 = fmaf(q.x, a.x, fmaf(q.y, a.y, fmaf(q.z, a.z, fmaf(q.w, a.w, s0))));
            s1 = fmaf(q.x, b.x, fmaf(q.y, b.y, fmaf(q.z, b.z, fmaf(q.w, b.w, s1))));
            s2 = fmaf(q.x, c.x, fmaf(q.y, c.y, fmaf(q.z, c.z, fmaf(q.w, c.w, s2))));
        }

        // butterfly {8,4}: stays within each 16-lane half
        #pragma unroll
        for (int off = 8; off >= 4; off >>= 1) {
            s0 += __shfl_xor_sync(0xffffffffu, s0, off);
            s1 += __shfl_xor_sync(0xffffffffu, s1, off);
            s2 += __shfl_xor_sync(0xffffffffu, s2, off);
        }
        // each 4-lane group (closed under xor {2,1}) finishes one tap
        float t = (grp == 0) ? s0 : (grp == 1) ? s1 : (grp == 2) ? s2 : s0;
        t += __shfl_xor_sync(0xffffffffu, t, 2);
        t += __shfl_xor_sync(0xffffffffu, t, 1);

        if ((lane & 3) == 0) {
            const float val = (grp < 3) ? (t + bias) : 0.0f;
            ((float*)&g_w[row])[grp] = val;   // 8 lanes -> 2 contiguous sectors
        }
    }
}

// ---------------- kernel 2: conv + LayerNorm (R2 version, proven) ----------------
__global__ __launch_bounds__(256, 4)
void dydw_conv_ln_kernel(const float* __restrict__ value,
                         const float* __restrict__ gamma,
                         const float* __restrict__ beta,
                         float* __restrict__ out)
{
    const int lane   = threadIdx.x & 31;
    const int warp   = (blockIdx.x * blockDim.x + threadIdx.x) >> 5;
    const int nwarps = (gridDim.x * blockDim.x) >> 5;
    const int cbase  = lane * 8;

    float gr[8], br[8];
    #pragma unroll
    for (int i = 0; i < 8; i++) {
        gr[i] = __ldg(&gamma[cbase + i]);
        br[i] = __ldg(&beta[cbase + i]);
    }

    for (int row = warp; row < ROWS_TOTAL; row += nwarps) {
        const float4 w4 = __ldg(&g_w[row]);   // uniform: 1 wavefront (L2 hit)
        const float k0 = w4.x, k1 = w4.y, k2 = w4.z;

        const float4* vrow = (const float4*)(value + (size_t)row * CH);
        const float4 v0 = vrow[lane * 2 + 0];
        const float4 v1 = vrow[lane * 2 + 1];
        const float v[8] = {v0.x, v0.y, v0.z, v0.w, v1.x, v1.y, v1.z, v1.w};

        // halo for the 3-tap conv (zero pad at row edges)
        float left  = __shfl_up_sync(0xffffffffu, v[7], 1);
        float right = __shfl_down_sync(0xffffffffu, v[0], 1);
        if (lane == 0)  left = 0.f;
        if (lane == 31) right = 0.f;

        float o[8];
        float sum = 0.f, sq = 0.f;
        #pragma unroll
        for (int i = 0; i < 8; i++) {
            const float vm = (i == 0) ? left  : v[i - 1];
            const float vp = (i == 7) ? right : v[i + 1];
            o[i] = fmaf(k0, vm, fmaf(k1, v[i], k2 * vp));
            sum += o[i];
            sq = fmaf(o[i], o[i], sq);
        }

        // grouped 2-value reduce: offset 16, then halves finish different values
        const float a = sum + __shfl_xor_sync(0xffffffffu, sum, 16);
        const float b = sq  + __shfl_xor_sync(0xffffffffu, sq,  16);
        float t = (lane < 16) ? a : b;
        #pragma unroll
        for (int off = 8; off; off >>= 1)
            t += __shfl_xor_sync(0xffffffffu, t, off);
        const float tot_sum = __shfl_sync(0xffffffffu, t, 0);
        const float tot_sq  = __shfl_sync(0xffffffffu, t, 16);

        const float mean = tot_sum * (1.f / CH);
        const float var  = tot_sq * (1.f / CH) - mean * mean;
        const float rstd = rsqrtf(var + LN_EPS);

        float y[8];
        #pragma unroll
        for (int i = 0; i < 8; i++)
            y[i] = fmaf((o[i] - mean) * rstd, gr[i], br[i]);

        float4* orow = (float4*)(out + (size_t)row * CH);
        orow[lane * 2 + 0] = make_float4(y[0], y[1], y[2], y[3]);
        orow[lane * 2 + 1] = make_float4(y[4], y[5], y[6], y[7]);
    }
}

extern "C" void kernel_launch(void* const* d_in, const int* in_sizes, int n_in,
                              void* d_out, int out_size)
{
    const float* query = (const float*)d_in[0];
    const float* value = (const float*)d_in[1];
    const float* W_w   = (const float*)d_in[2];
    const float* b_w   = (const float*)d_in[3];
    const float* gamma = (const float*)d_in[4];
    const float* beta  = (const float*)d_in[5];
    float* out = (float*)d_out;

    dydw_wcalc_kernel<<<1600, 256>>>(query, W_w, b_w);            // 2 rows/warp/iter
    dydw_conv_ln_kernel<<<1600, 256>>>(value, gamma, beta, out);  // 8 rows/warp
}

// round 9
// speedup vs baseline: 1.0627x; 1.0255x over previous
#include <cuda_runtime.h>

// DyDepthwiseConvAtten: B=1024, N=100, C=256, K=3
//   K1 (wcalc): half-warp per row, W streamed from L1, 4 SHFL/row.
//   K2 (conv+LN): R2 per-row code (proven), persistent one-wave grid.
// R9 change: grid = 740 = 148 SMs x 5 resident blocks (48 regs) -> exactly
// one wave, no tail (previous 1600-block launch was 2.16 waves).

#define ROWS_TOTAL (1024 * 100)
#define CH 256
#define LN_EPS 1e-5f
#define GRID_1WAVE 740

// per-row conv taps (k0,k1,k2,pad) — 1.6 MB scratch, L2-resident
__device__ float4 g_w[ROWS_TOTAL];

// ---------------- kernel 1: dynamic taps, half-warp per row ----------------
__global__ __launch_bounds__(256, 5)
void dydw_wcalc_kernel(const float* __restrict__ query,
                       const float* __restrict__ W_w,
                       const float* __restrict__ b_w)
{
    const int lane    = threadIdx.x & 31;
    const int half    = lane >> 4;
    const int warp    = (blockIdx.x * blockDim.x + threadIdx.x) >> 5;
    const int nwarps  = (gridDim.x * blockDim.x) >> 5;
    const int cbase4  = (lane & 15) * 4;

    const float4* W0 = (const float4*)W_w + cbase4;        // tap 0, this lane's 16 ch
    const float4* W1 = (const float4*)W_w + 64 + cbase4;   // tap 1
    const float4* W2 = (const float4*)W_w + 128 + cbase4;  // tap 2

    const int grp = (lane >> 2) & 3;
    const float bias = (grp < 3) ? __ldg(&b_w[grp]) : 0.0f;

    for (int rp = warp * 2; rp < ROWS_TOTAL; rp += 2 * nwarps) {
        const int row = rp + half;
        const float4* qrow = (const float4*)(query + (size_t)row * CH);

        // issue all 4 q loads up front (MLP=4, DRAM stream)
        float4 q4[4];
        #pragma unroll
        for (int i = 0; i < 4; i++) q4[i] = qrow[cbase4 + i];

        float s0 = 0.f, s1 = 0.f, s2 = 0.f;
        #pragma unroll
        for (int i = 0; i < 4; i++) {
            const float4 a = __ldg(&W0[i]);    // L1-resident (3KB total)
            const float4 b = __ldg(&W1[i]);
            const float4 c = __ldg(&W2[i]);
            const float4 q = q4[i];
            s0 = fmaf(q.x, a.x, fmaf(q.y, a.y, fmaf(q.z, a.z, fmaf(q.w, a.w, s0))));
            s1 = fmaf(q.x, b.x, fmaf(q.y, b.y, fmaf(q.z, b.z, fmaf(q.w, b.w, s1))));
            s2 = fmaf(q.x, c.x, fmaf(q.y, c.y, fmaf(q.z, c.z, fmaf(q.w, c.w, s2))));
        }

        // butterfly {8,4}: stays within each 16-lane half
        #pragma unroll
        for (int off = 8; off >= 4; off >>= 1) {
            s0 += __shfl_xor_sync(0xffffffffu, s0, off);
            s1 += __shfl_xor_sync(0xffffffffu, s1, off);
            s2 += __shfl_xor_sync(0xffffffffu, s2, off);
        }
        // each 4-lane group (closed under xor {2,1}) finishes one tap
        float t = (grp == 0) ? s0 : (grp == 1) ? s1 : (grp == 2) ? s2 : s0;
        t += __shfl_xor_sync(0xffffffffu, t, 2);
        t += __shfl_xor_sync(0xffffffffu, t, 1);

        if ((lane & 3) == 0) {
            const float val = (grp < 3) ? (t + bias) : 0.0f;
            ((float*)&g_w[row])[grp] = val;   // 8 lanes -> 2 contiguous sectors
        }
    }
}

// ---------------- kernel 2: conv + LayerNorm ----------------
__global__ __launch_bounds__(256, 5)
void dydw_conv_ln_kernel(const float* __restrict__ value,
                         const float* __restrict__ gamma,
                         const float* __restrict__ beta,
                         float* __restrict__ out)
{
    const int lane   = threadIdx.x & 31;
    const int warp   = (blockIdx.x * blockDim.x + threadIdx.x) >> 5;
    const int nwarps = (gridDim.x * blockDim.x) >> 5;
    const int cbase  = lane * 8;

    float gr[8], br[8];
    #pragma unroll
    for (int i = 0; i < 8; i++) {
        gr[i] = __ldg(&gamma[cbase + i]);
        br[i] = __ldg(&beta[cbase + i]);
    }

    for (int row = warp; row < ROWS_TOTAL; row += nwarps) {
        const float4 w4 = __ldg(&g_w[row]);   // uniform: 1 wavefront (L2 hit)
        const float k0 = w4.x, k1 = w4.y, k2 = w4.z;

        const float4* vrow = (const float4*)(value + (size_t)row * CH);
        const float4 v0 = vrow[lane * 2 + 0];
        const float4 v1 = vrow[lane * 2 + 1];
        const float v[8] = {v0.x, v0.y, v0.z, v0.w, v1.x, v1.y, v1.z, v1.w};

        // halo for the 3-tap conv (zero pad at row edges)
        float left  = __shfl_up_sync(0xffffffffu, v[7], 1);
        float right = __shfl_down_sync(0xffffffffu, v[0], 1);
        if (lane == 0)  left = 0.f;
        if (lane == 31) right = 0.f;

        float o[8];
        float sum = 0.f, sq = 0.f;
        #pragma unroll
        for (int i = 0; i < 8; i++) {
            const float vm = (i == 0) ? left  : v[i - 1];
            const float vp = (i == 7) ? right : v[i + 1];
            o[i] = fmaf(k0, vm, fmaf(k1, v[i], k2 * vp));
            sum += o[i];
            sq = fmaf(o[i], o[i], sq);
        }

        // grouped 2-value reduce: offset 16, then halves finish different values
        const float a = sum + __shfl_xor_sync(0xffffffffu, sum, 16);
        const float b = sq  + __shfl_xor_sync(0xffffffffu, sq,  16);
        float t = (lane < 16) ? a : b;
        #pragma unroll
        for (int off = 8; off; off >>= 1)
            t += __shfl_xor_sync(0xffffffffu, t, off);
        const float tot_sum = __shfl_sync(0xffffffffu, t, 0);
        const float tot_sq  = __shfl_sync(0xffffffffu, t, 16);

        const float mean = tot_sum * (1.f / CH);
        const float var  = tot_sq * (1.f / CH) - mean * mean;
        const float rstd = rsqrtf(var + LN_EPS);

        float y[8];
        #pragma unroll
        for (int i = 0; i < 8; i++)
            y[i] = fmaf((o[i] - mean) * rstd, gr[i], br[i]);

        float4* orow = (float4*)(out + (size_t)row * CH);
        orow[lane * 2 + 0] = make_float4(y[0], y[1], y[2], y[3]);
        orow[lane * 2 + 1] = make_float4(y[4], y[5], y[6], y[7]);
    }
}

extern "C" void kernel_launch(void* const* d_in, const int* in_sizes, int n_in,
                              void* d_out, int out_size)
{
    const float* query = (const float*)d_in[0];
    const float* value = (const float*)d_in[1];
    const float* W_w   = (const float*)d_in[2];
    const float* b_w   = (const float*)d_in[3];
    const float* gamma = (const float*)d_in[4];
    const float* beta  = (const float*)d_in[5];
    float* out = (float*)d_out;

    // one full wave: 148 SMs x 5 blocks of 256 threads (48 regs/thread)
    dydw_wcalc_kernel<<<GRID_1WAVE, 256>>>(query, W_w, b_w);
    dydw_conv_ln_kernel<<<GRID_1WAVE, 256>>>(value, gamma, beta, out);
}